// round 8
// baseline (speedup 1.0000x reference)
#include <cuda_runtime.h>

#define D 128
#define TILE_M 64
#define KB 32
#define MAXN 50176
#define MAXE 524288
#define SCAN_B 1024

typedef unsigned long long u64;

// packed 2xfp32 FMA: acc = a*b + acc  (FFMA2, sm_103a)
#define FMA2(acc, a, b) \
    asm("fma.rn.f32x2 %0, %1, %2, %0;" : "+l"(acc) : "l"(a), "l"(b))
#define DUP_F32(d, s) \
    asm("mov.b64 %0, {%1, %1};" : "=l"(d) : "f"(s))
#define UNPACK2(lo, hi, p) \
    asm("mov.b64 {%0, %1}, %2;" : "=f"(lo), "=f"(hi) : "l"(p))

// ---- device scratch (no allocations allowed) ----
__device__ float g_agg[MAXN * D];   // x + sum(relu(x_src+ea)) per node
__device__ float g_h[MAXN * D];
__device__ float g_x1[MAXN * D];
__device__ float g_sum[D];
__device__ float g_sq[D];
__device__ float g_scale[D];
__device__ float g_shift[D];
// CSR build scratch
__device__ int g_cnt[MAXN];
__device__ int g_rowptr[MAXN];
__device__ int g_fill[MAXN];      // after scatter: row end
__device__ int g_perm[MAXE];      // CSR-ordered original edge id (for ea)
__device__ int g_se[MAXE];        // CSR-ordered src node id
__device__ int g_bsum[64];

// ================= CSR build (once per launch, 5 kernels) =================
__global__ void zero_cnt_kernel(int* __restrict__ cnt, int n) {
    int i = blockIdx.x * blockDim.x + threadIdx.x;
    if (i < n) cnt[i] = 0;
}

__global__ void hist_kernel(const int* __restrict__ ei, int* __restrict__ cnt, int E) {
    int i = blockIdx.x * blockDim.x + threadIdx.x;
    if (i < E) atomicAdd(&cnt[__ldg(ei + E + i)], 1);
}

__global__ __launch_bounds__(SCAN_B) void scan1_kernel(
    const int* __restrict__ cnt, int* __restrict__ rowptr,
    int* __restrict__ bsum, int n)
{
    __shared__ int sh[SCAN_B];
    int t = threadIdx.x;
    int i = blockIdx.x * SCAN_B + t;
    int v = (i < n) ? cnt[i] : 0;
    sh[t] = v;
    __syncthreads();
#pragma unroll
    for (int off = 1; off < SCAN_B; off <<= 1) {
        int add = (t >= off) ? sh[t - off] : 0;
        __syncthreads();
        sh[t] += add;
        __syncthreads();
    }
    if (i < n) rowptr[i] = sh[t] - v;
    if (t == SCAN_B - 1) bsum[blockIdx.x] = sh[t];
}

// scan2 merged in: each block sums bsum[0..blockIdx.x) itself (<= 49 ints)
__global__ __launch_bounds__(SCAN_B) void scan23_kernel(
    int* __restrict__ rowptr, int* __restrict__ fill,
    const int* __restrict__ bsum, int n)
{
    __shared__ int boff_s;
    if (threadIdx.x == 0) {
        int acc = 0;
        for (int b = 0; b < blockIdx.x; b++) acc += bsum[b];
        boff_s = acc;
    }
    __syncthreads();
    int i = blockIdx.x * SCAN_B + threadIdx.x;
    if (i < n) {
        int r = rowptr[i] + boff_s;
        rowptr[i] = r;
        fill[i] = r;
    }
}

// scatter: writes BOTH the original edge id and the src id in CSR order
__global__ void scatter_kernel(const int* __restrict__ ei, int* __restrict__ fill,
                               int* __restrict__ perm, int* __restrict__ se, int E) {
    int e = blockIdx.x * blockDim.x + threadIdx.x;
    if (e < E) {
        int s = __ldg(ei + e);
        int d = __ldg(ei + E + e);
        int idx = atomicAdd(&fill[d], 1);
        perm[idx] = e;
        se[idx] = s;
    }
}

// ========== per-layer aggregate: warp handles TWO adjacent nodes, interleaved ==========
// agg[v] = x[v] + sum_{e: dst=v} relu(x[src_e] + ea[e]); also zeroes BN stats
__global__ __launch_bounds__(256) void agg_kernel(
    const float* __restrict__ x,
    const float* __restrict__ ea,
    const int* __restrict__ rowptr, const int* __restrict__ rowend,
    const int* __restrict__ perm, const int* __restrict__ se,
    float* __restrict__ agg, float* __restrict__ ssum, float* __restrict__ ssq, int N)
{
    if (blockIdx.x == 0 && threadIdx.x < D) {
        ssum[threadIdx.x] = 0.f;
        ssq[threadIdx.x] = 0.f;
    }
    int pair = blockIdx.x * 8 + (threadIdx.x >> 5);
    int v0 = pair * 2;
    if (v0 >= N) return;
    int v1 = v0 + 1;
    bool has1 = (v1 < N);
    int lane = threadIdx.x & 31;

    int j0   = __ldg(rowptr + v0);
    int end0 = __ldg(rowend + v0);
    int j1   = has1 ? __ldg(rowptr + v1) : 0;
    int end1 = has1 ? __ldg(rowend + v1) : 0;

    const float4* x4  = (const float4*)x;
    const float4* ea4 = (const float4*)ea;
    float4 acc0 = __ldg(x4 + (size_t)v0 * 32 + lane);
    float4 acc1 = has1 ? __ldg(x4 + (size_t)v1 * 32 + lane)
                       : make_float4(0.f, 0.f, 0.f, 0.f);

    while (j0 < end0 || j1 < end1) {
        bool a0 = (j0 < end0), a1 = (j1 < end1);   // warp-uniform
        float4 xv0, ev0, xv1, ev1;
        if (a0) {
            int e0 = __ldg(perm + j0);
            int s0 = __ldg(se + j0);
            xv0 = __ldg(x4 + (size_t)s0 * 32 + lane);
            ev0 = __ldg(ea4 + (size_t)e0 * 32 + lane);
        }
        if (a1) {
            int e1 = __ldg(perm + j1);
            int s1 = __ldg(se + j1);
            xv1 = __ldg(x4 + (size_t)s1 * 32 + lane);
            ev1 = __ldg(ea4 + (size_t)e1 * 32 + lane);
        }
        if (a0) {
            acc0.x += fmaxf(xv0.x + ev0.x, 0.f);
            acc0.y += fmaxf(xv0.y + ev0.y, 0.f);
            acc0.z += fmaxf(xv0.z + ev0.z, 0.f);
            acc0.w += fmaxf(xv0.w + ev0.w, 0.f);
            j0++;
        }
        if (a1) {
            acc1.x += fmaxf(xv1.x + ev1.x, 0.f);
            acc1.y += fmaxf(xv1.y + ev1.y, 0.f);
            acc1.z += fmaxf(xv1.z + ev1.z, 0.f);
            acc1.w += fmaxf(xv1.w + ev1.w, 0.f);
            j1++;
        }
    }
    ((float4*)agg)[(size_t)v0 * 32 + lane] = acc0;
    if (has1) ((float4*)agg)[(size_t)v1 * 32 + lane] = acc1;
}

// ---- fused GEMM (FFMA2 inner loop):
//  MODE 0 = A@W1+b1, write h, accumulate BN stats   (A = x+agg precombined)
//  MODE 1 = relu(A*scale+shift)@W2+b2, relu, write out ----
template<int MODE>
__global__ __launch_bounds__(128)
void gemm_kernel(const float* __restrict__ A,
                 const float* __restrict__ W, const float* __restrict__ bias,
                 const float* __restrict__ scale, const float* __restrict__ shift,
                 float* __restrict__ out,
                 float* __restrict__ ssum, float* __restrict__ ssq, int M)
{
    __shared__ float W_s[KB][D];
    __shared__ float t_s[KB][TILE_M + 4];
    __shared__ float bn_s[2][D];
    __shared__ float st_s[2][D];

    int t = threadIdx.x;
    int cg = t >> 3;
    int rg = t & 7;
    int row_base = blockIdx.x * TILE_M;

    if (MODE == 1) {
        bn_s[0][t] = __ldg(scale + t);
        bn_s[1][t] = __ldg(shift + t);
        __syncthreads();
    }

    u64 accp[8][4];
#pragma unroll
    for (int r = 0; r < 8; r++)
#pragma unroll
        for (int c = 0; c < 4; c++) accp[r][c] = 0ULL;

    for (int kb = 0; kb < D; kb += KB) {
#pragma unroll
        for (int i = 0; i < 8; i++) {
            int f4 = i * 128 + t;
            int k  = f4 >> 5;
            int c4 = f4 & 31;
            float4 w = __ldg((const float4*)(W + (size_t)(kb + k) * D) + c4);
            *((float4*)&W_s[k][c4 * 4]) = w;
        }
#pragma unroll
        for (int i = 0; i < 4; i++) {
            int f4 = i * 128 + t;
            int r  = f4 >> 3;
            int k4 = f4 & 7;
            int grow = row_base + r;
            float4 v = make_float4(0.f, 0.f, 0.f, 0.f);
            if (grow < M) {
                float4 a = __ldg((const float4*)(A + (size_t)grow * D + kb) + k4);
                if (MODE == 0) {
                    v = a;
                } else {
                    int k0 = kb + k4 * 4;
                    v.x = fmaxf(fmaf(a.x, bn_s[0][k0 + 0], bn_s[1][k0 + 0]), 0.f);
                    v.y = fmaxf(fmaf(a.y, bn_s[0][k0 + 1], bn_s[1][k0 + 1]), 0.f);
                    v.z = fmaxf(fmaf(a.z, bn_s[0][k0 + 2], bn_s[1][k0 + 2]), 0.f);
                    v.w = fmaxf(fmaf(a.w, bn_s[0][k0 + 3], bn_s[1][k0 + 3]), 0.f);
                }
            }
            int kk = k4 * 4;
            t_s[kk + 0][r] = v.x;
            t_s[kk + 1][r] = v.y;
            t_s[kk + 2][r] = v.z;
            t_s[kk + 3][r] = v.w;
        }
        __syncthreads();

#pragma unroll 8
        for (int k = 0; k < KB; k++) {
            float a[8];
            const float4* ap = (const float4*)&t_s[k][rg * 8];
            *(float4*)&a[0] = ap[0];
            *(float4*)&a[4] = ap[1];
            ulonglong2 w01 = *(const ulonglong2*)&W_s[k][cg * 8];
            ulonglong2 w23 = *(const ulonglong2*)&W_s[k][cg * 8 + 4];
            u64 wp0 = w01.x, wp1 = w01.y, wp2 = w23.x, wp3 = w23.y;
#pragma unroll
            for (int r = 0; r < 8; r++) {
                u64 ad;
                DUP_F32(ad, a[r]);
                FMA2(accp[r][0], ad, wp0);
                FMA2(accp[r][1], ad, wp1);
                FMA2(accp[r][2], ad, wp2);
                FMA2(accp[r][3], ad, wp3);
            }
        }
        __syncthreads();
    }

    float bv[8];
#pragma unroll
    for (int c = 0; c < 8; c++) bv[c] = __ldg(bias + cg * 8 + c);

    if (MODE == 0) {
        st_s[0][t] = 0.f;
        st_s[1][t] = 0.f;
        __syncthreads();
        float csum[8], csq[8];
#pragma unroll
        for (int c = 0; c < 8; c++) { csum[c] = 0.f; csq[c] = 0.f; }
#pragma unroll
        for (int r = 0; r < 8; r++) {
            int row = row_base + rg * 8 + r;
            if (row < M) {
                float o[8];
#pragma unroll
                for (int cp = 0; cp < 4; cp++)
                    UNPACK2(o[2 * cp], o[2 * cp + 1], accp[r][cp]);
#pragma unroll
                for (int c = 0; c < 8; c++) {
                    o[c] += bv[c];
                    csum[c] += o[c];
                    csq[c]  += o[c] * o[c];
                }
                float4* op = (float4*)(out + (size_t)row * D + cg * 8);
                op[0] = make_float4(o[0], o[1], o[2], o[3]);
                op[1] = make_float4(o[4], o[5], o[6], o[7]);
            }
        }
#pragma unroll
        for (int c = 0; c < 8; c++) {
            atomicAdd(&st_s[0][cg * 8 + c], csum[c]);
            atomicAdd(&st_s[1][cg * 8 + c], csq[c]);
        }
        __syncthreads();
        atomicAdd(&ssum[t], st_s[0][t]);
        atomicAdd(&ssq[t],  st_s[1][t]);
    } else {
#pragma unroll
        for (int r = 0; r < 8; r++) {
            int row = row_base + rg * 8 + r;
            if (row < M) {
                float o[8];
#pragma unroll
                for (int cp = 0; cp < 4; cp++)
                    UNPACK2(o[2 * cp], o[2 * cp + 1], accp[r][cp]);
#pragma unroll
                for (int c = 0; c < 8; c++) o[c] = fmaxf(o[c] + bv[c], 0.f);
                float4* op = (float4*)(out + (size_t)row * D + cg * 8);
                op[0] = make_float4(o[0], o[1], o[2], o[3]);
                op[1] = make_float4(o[4], o[5], o[6], o[7]);
            }
        }
    }
}

// ---- fold BN stats + gamma/beta into per-feature scale/shift ----
__global__ void finalize_kernel(const float* __restrict__ ssum, const float* __restrict__ ssq,
                                const float* __restrict__ gamma, const float* __restrict__ beta,
                                float* __restrict__ scale, float* __restrict__ shift, float invN)
{
    int i = threadIdx.x;
    float m  = ssum[i] * invN;
    float v  = fmaf(ssq[i], invN, -m * m);
    float r  = rsqrtf(v + 1e-5f);
    float sc = r * __ldg(gamma + i);
    scale[i] = sc;
    shift[i] = fmaf(-m, sc, __ldg(beta + i));
}

extern "C" void kernel_launch(void* const* d_in, const int* in_sizes, int n_in,
                              void* d_out, int out_size) {
    const float* x     = (const float*)d_in[0];
    const int*   ei    = (const int*)d_in[1];       // int32 (JAX demotes int64)
    const float* ea    = (const float*)d_in[2];
    const float* W1    = (const float*)d_in[3];
    const float* b1    = (const float*)d_in[4];
    const float* gamma = (const float*)d_in[5];
    const float* beta  = (const float*)d_in[6];
    const float* W2    = (const float*)d_in[7];
    const float* b2    = (const float*)d_in[8];

    int M = in_sizes[0] / D;      // nodes
    int E = in_sizes[2] / D;      // edges
    int L = in_sizes[3] / (D * D);

    float *p_agg, *p_h, *p_x1, *p_sum, *p_sq, *p_scale, *p_shift;
    int *p_cnt, *p_rowptr, *p_fill, *p_perm, *p_se, *p_bsum;
    cudaGetSymbolAddress((void**)&p_agg,   g_agg);
    cudaGetSymbolAddress((void**)&p_h,     g_h);
    cudaGetSymbolAddress((void**)&p_x1,    g_x1);
    cudaGetSymbolAddress((void**)&p_sum,   g_sum);
    cudaGetSymbolAddress((void**)&p_sq,    g_sq);
    cudaGetSymbolAddress((void**)&p_scale, g_scale);
    cudaGetSymbolAddress((void**)&p_shift, g_shift);
    cudaGetSymbolAddress((void**)&p_cnt,    g_cnt);
    cudaGetSymbolAddress((void**)&p_rowptr, g_rowptr);
    cudaGetSymbolAddress((void**)&p_fill,   g_fill);
    cudaGetSymbolAddress((void**)&p_perm,   g_perm);
    cudaGetSymbolAddress((void**)&p_se,     g_se);
    cudaGetSymbolAddress((void**)&p_bsum,   g_bsum);

    int gemm_blocks = (M + TILE_M - 1) / TILE_M;
    int eb = (E + 255) / 256;
    int nb256 = (M + 255) / 256;
    int nbscan = (M + SCAN_B - 1) / SCAN_B;
    int agg_blocks = (M + 15) / 16;   // 8 warps/block x 2 nodes/warp

    // ---- build CSR once ----
    zero_cnt_kernel<<<nb256, 256>>>(p_cnt, M);
    hist_kernel<<<eb, 256>>>(ei, p_cnt, E);
    scan1_kernel<<<nbscan, SCAN_B>>>(p_cnt, p_rowptr, p_bsum, M);
    scan23_kernel<<<nbscan, SCAN_B>>>(p_rowptr, p_fill, p_bsum, M);
    scatter_kernel<<<eb, 256>>>(ei, p_fill, p_perm, p_se, E);
    // after scatter: p_fill[v] == row end of v

    for (int l = 0; l < L; l++) {
        const float* xin = (l == 0) ? x : p_x1;
        float* xout = (l == L - 1) ? (float*)d_out : p_x1;

        agg_kernel<<<agg_blocks, 256>>>(xin, ea, p_rowptr, p_fill, p_perm, p_se,
                                        p_agg, p_sum, p_sq, M);
        gemm_kernel<0><<<gemm_blocks, 128>>>(p_agg,
                                             W1 + (size_t)l * D * D, b1 + (size_t)l * D,
                                             nullptr, nullptr, p_h, p_sum, p_sq, M);
        finalize_kernel<<<1, D>>>(p_sum, p_sq, gamma + (size_t)l * D, beta + (size_t)l * D,
                                  p_scale, p_shift, 1.0f / (float)M);
        gemm_kernel<1><<<gemm_blocks, 128>>>(p_h,
                                             W2 + (size_t)l * D * D, b2 + (size_t)l * D,
                                             p_scale, p_shift, xout, nullptr, nullptr, M);
    }
}

// round 9
// speedup vs baseline: 1.0772x; 1.0772x over previous
#include <cuda_runtime.h>

#define D 128
#define TILE_M 64
#define KB 32
#define MAXN 50176
#define MAXE 524288
#define SCAN_B 1024
#define PIPE 4

typedef unsigned long long u64;

// packed 2xfp32 FMA: acc = a*b + acc  (FFMA2, sm_103a)
#define FMA2(acc, a, b) \
    asm("fma.rn.f32x2 %0, %1, %2, %0;" : "+l"(acc) : "l"(a), "l"(b))
#define DUP_F32(d, s) \
    asm("mov.b64 %0, {%1, %1};" : "=l"(d) : "f"(s))
#define UNPACK2(lo, hi, p) \
    asm("mov.b64 {%0, %1}, %2;" : "=f"(lo), "=f"(hi) : "l"(p))

__device__ __forceinline__ void cpa16(unsigned int dst, const void* src) {
    asm volatile("cp.async.cg.shared.global [%0], [%1], 16;" :: "r"(dst), "l"(src));
}
#define CP_COMMIT() asm volatile("cp.async.commit_group;" ::: "memory")
#define CP_WAIT(n)  asm volatile("cp.async.wait_group %0;" :: "n"(n) : "memory")

// ---- device scratch (no allocations allowed) ----
__device__ float g_agg[MAXN * D];   // x + sum(relu(x_src+ea)) per node
__device__ float g_h[MAXN * D];
__device__ float g_x1[MAXN * D];
__device__ float g_sum[D];
__device__ float g_sq[D];
__device__ float g_scale[D];
__device__ float g_shift[D];
// CSR build scratch
__device__ int g_cnt[MAXN];       // zero at module load; re-zeroed by scatter each launch
__device__ int g_rowptr[MAXN];
__device__ int g_fill[MAXN];      // after scatter: row end
__device__ int g_perm[MAXE];      // CSR-ordered original edge id (for ea)
__device__ int g_se[MAXE];        // CSR-ordered src node id
__device__ int g_bsum[64];

// ================= CSR build (once per launch, 4 kernels) =================
__global__ void hist_kernel(const int* __restrict__ ei, int* __restrict__ cnt, int E) {
    int i = blockIdx.x * blockDim.x + threadIdx.x;
    if (i < E) atomicAdd(&cnt[__ldg(ei + E + i)], 1);
}

__global__ __launch_bounds__(SCAN_B) void scan1_kernel(
    const int* __restrict__ cnt, int* __restrict__ rowptr,
    int* __restrict__ bsum, int n)
{
    __shared__ int sh[SCAN_B];
    int t = threadIdx.x;
    int i = blockIdx.x * SCAN_B + t;
    int v = (i < n) ? cnt[i] : 0;
    sh[t] = v;
    __syncthreads();
#pragma unroll
    for (int off = 1; off < SCAN_B; off <<= 1) {
        int add = (t >= off) ? sh[t - off] : 0;
        __syncthreads();
        sh[t] += add;
        __syncthreads();
    }
    if (i < n) rowptr[i] = sh[t] - v;
    if (t == SCAN_B - 1) bsum[blockIdx.x] = sh[t];
}

// scan2 merged in: each block sums bsum[0..blockIdx.x) itself (<= 49 ints)
__global__ __launch_bounds__(SCAN_B) void scan23_kernel(
    int* __restrict__ rowptr, int* __restrict__ fill,
    const int* __restrict__ bsum, int n)
{
    __shared__ int boff_s;
    if (threadIdx.x == 0) {
        int acc = 0;
        for (int b = 0; b < blockIdx.x; b++) acc += bsum[b];
        boff_s = acc;
    }
    __syncthreads();
    int i = blockIdx.x * SCAN_B + threadIdx.x;
    if (i < n) {
        int r = rowptr[i] + boff_s;
        rowptr[i] = r;
        fill[i] = r;
    }
}

// scatter: write edge id + src id in CSR order; also re-zero cnt for next replay
__global__ void scatter_kernel(const int* __restrict__ ei, int* __restrict__ fill,
                               int* __restrict__ perm, int* __restrict__ se,
                               int* __restrict__ cnt, int E, int N) {
    int e = blockIdx.x * blockDim.x + threadIdx.x;
    if (e < N) cnt[e] = 0;                       // cnt consumed by scan1; reset for next launch
    if (e < E) {
        int s = __ldg(ei + e);
        int d = __ldg(ei + E + e);
        int idx = atomicAdd(&fill[d], 1);
        perm[idx] = e;
        se[idx] = s;
    }
}

// ========== per-layer aggregate: warp per node, cp.async 4-deep pipeline ==========
// agg[v] = x[v] + sum_{e: dst=v} relu(x[src_e] + ea[e]); also zeroes BN stats
__global__ __launch_bounds__(256) void agg_kernel(
    const float* __restrict__ x,
    const float* __restrict__ ea,
    const int* __restrict__ rowptr, const int* __restrict__ rowend,
    const int* __restrict__ perm, const int* __restrict__ se,
    float* __restrict__ agg, float* __restrict__ ssum, float* __restrict__ ssq, int N)
{
    __shared__ float4 buf[8][PIPE][2][32];   // 32 KB: warp, slot, {x,ea}, lane

    if (blockIdx.x == 0 && threadIdx.x < D) {
        ssum[threadIdx.x] = 0.f;
        ssq[threadIdx.x] = 0.f;
    }
    int w = threadIdx.x >> 5;
    int lane = threadIdx.x & 31;
    int v = blockIdx.x * 8 + w;
    if (v >= N) return;

    int j   = __ldg(rowptr + v);
    int end = __ldg(rowend + v);
    int deg = end - j;

    const float4* x4  = (const float4*)x;
    const float4* ea4 = (const float4*)ea;
    float4 acc = __ldg(x4 + (size_t)v * 32 + lane);

    unsigned int bx = (unsigned int)__cvta_generic_to_shared(&buf[w][0][0][lane]);
    // slot p: x part at bx + p*1024, ea part at bx + p*1024 + 512

    // prologue: ALWAYS commit PIPE groups (empty if deg < PIPE) so group
    // arithmetic in the steady loop is exact.
#pragma unroll
    for (int p = 0; p < PIPE; p++) {
        if (p < deg) {
            int e = __ldg(perm + j + p);
            int s = __ldg(se + j + p);
            cpa16(bx + p * 1024,       x4  + (size_t)s * 32 + lane);
            cpa16(bx + p * 1024 + 512, ea4 + (size_t)e * 32 + lane);
        }
        CP_COMMIT();
    }

    int slot = 0;
    for (int i = 0; i < deg; i++) {
        // hoist next-edge index loads above the wait (overlap L1 latency)
        int nj = j + i + PIPE;
        bool isu = (nj < end);               // warp-uniform
        int e = 0, s = 0;
        if (isu) {
            e = __ldg(perm + nj);
            s = __ldg(se + nj);
        }
        CP_WAIT(PIPE - 1);                    // group i complete -> slot data ready
        float4 xv = buf[w][slot][0][lane];
        float4 ev = buf[w][slot][1][lane];
        if (isu) {
            cpa16(bx + slot * 1024,       x4  + (size_t)s * 32 + lane);
            cpa16(bx + slot * 1024 + 512, ea4 + (size_t)e * 32 + lane);
        }
        CP_COMMIT();                          // one group per iteration, always
        acc.x += fmaxf(xv.x + ev.x, 0.f);
        acc.y += fmaxf(xv.y + ev.y, 0.f);
        acc.z += fmaxf(xv.z + ev.z, 0.f);
        acc.w += fmaxf(xv.w + ev.w, 0.f);
        slot = (slot + 1) & (PIPE - 1);
    }
    asm volatile("cp.async.wait_all;" ::: "memory");
    ((float4*)agg)[(size_t)v * 32 + lane] = acc;
}

// ---- fused GEMM (FFMA2 inner loop):
//  MODE 0 = A@W1+b1, write h, accumulate BN stats   (A = x+agg precombined)
//  MODE 1 = relu(A*scale+shift)@W2+b2, relu, write out ----
template<int MODE>
__global__ __launch_bounds__(128)
void gemm_kernel(const float* __restrict__ A,
                 const float* __restrict__ W, const float* __restrict__ bias,
                 const float* __restrict__ scale, const float* __restrict__ shift,
                 float* __restrict__ out,
                 float* __restrict__ ssum, float* __restrict__ ssq, int M)
{
    __shared__ float W_s[KB][D];
    __shared__ float t_s[KB][TILE_M + 4];
    __shared__ float bn_s[2][D];
    __shared__ float st_s[2][D];

    int t = threadIdx.x;
    int cg = t >> 3;
    int rg = t & 7;
    int row_base = blockIdx.x * TILE_M;

    if (MODE == 1) {
        bn_s[0][t] = __ldg(scale + t);
        bn_s[1][t] = __ldg(shift + t);
        __syncthreads();
    }

    u64 accp[8][4];
#pragma unroll
    for (int r = 0; r < 8; r++)
#pragma unroll
        for (int c = 0; c < 4; c++) accp[r][c] = 0ULL;

    for (int kb = 0; kb < D; kb += KB) {
#pragma unroll
        for (int i = 0; i < 8; i++) {
            int f4 = i * 128 + t;
            int k  = f4 >> 5;
            int c4 = f4 & 31;
            float4 w = __ldg((const float4*)(W + (size_t)(kb + k) * D) + c4);
            *((float4*)&W_s[k][c4 * 4]) = w;
        }
#pragma unroll
        for (int i = 0; i < 4; i++) {
            int f4 = i * 128 + t;
            int r  = f4 >> 3;
            int k4 = f4 & 7;
            int grow = row_base + r;
            float4 v = make_float4(0.f, 0.f, 0.f, 0.f);
            if (grow < M) {
                float4 a = __ldg((const float4*)(A + (size_t)grow * D + kb) + k4);
                if (MODE == 0) {
                    v = a;
                } else {
                    int k0 = kb + k4 * 4;
                    v.x = fmaxf(fmaf(a.x, bn_s[0][k0 + 0], bn_s[1][k0 + 0]), 0.f);
                    v.y = fmaxf(fmaf(a.y, bn_s[0][k0 + 1], bn_s[1][k0 + 1]), 0.f);
                    v.z = fmaxf(fmaf(a.z, bn_s[0][k0 + 2], bn_s[1][k0 + 2]), 0.f);
                    v.w = fmaxf(fmaf(a.w, bn_s[0][k0 + 3], bn_s[1][k0 + 3]), 0.f);
                }
            }
            int kk = k4 * 4;
            t_s[kk + 0][r] = v.x;
            t_s[kk + 1][r] = v.y;
            t_s[kk + 2][r] = v.z;
            t_s[kk + 3][r] = v.w;
        }
        __syncthreads();

#pragma unroll 8
        for (int k = 0; k < KB; k++) {
            float a[8];
            const float4* ap = (const float4*)&t_s[k][rg * 8];
            *(float4*)&a[0] = ap[0];
            *(float4*)&a[4] = ap[1];
            ulonglong2 w01 = *(const ulonglong2*)&W_s[k][cg * 8];
            ulonglong2 w23 = *(const ulonglong2*)&W_s[k][cg * 8 + 4];
            u64 wp0 = w01.x, wp1 = w01.y, wp2 = w23.x, wp3 = w23.y;
#pragma unroll
            for (int r = 0; r < 8; r++) {
                u64 ad;
                DUP_F32(ad, a[r]);
                FMA2(accp[r][0], ad, wp0);
                FMA2(accp[r][1], ad, wp1);
                FMA2(accp[r][2], ad, wp2);
                FMA2(accp[r][3], ad, wp3);
            }
        }
        __syncthreads();
    }

    float bv[8];
#pragma unroll
    for (int c = 0; c < 8; c++) bv[c] = __ldg(bias + cg * 8 + c);

    if (MODE == 0) {
        st_s[0][t] = 0.f;
        st_s[1][t] = 0.f;
        __syncthreads();
        float csum[8], csq[8];
#pragma unroll
        for (int c = 0; c < 8; c++) { csum[c] = 0.f; csq[c] = 0.f; }
#pragma unroll
        for (int r = 0; r < 8; r++) {
            int row = row_base + rg * 8 + r;
            if (row < M) {
                float o[8];
#pragma unroll
                for (int cp = 0; cp < 4; cp++)
                    UNPACK2(o[2 * cp], o[2 * cp + 1], accp[r][cp]);
#pragma unroll
                for (int c = 0; c < 8; c++) {
                    o[c] += bv[c];
                    csum[c] += o[c];
                    csq[c]  += o[c] * o[c];
                }
                float4* op = (float4*)(out + (size_t)row * D + cg * 8);
                op[0] = make_float4(o[0], o[1], o[2], o[3]);
                op[1] = make_float4(o[4], o[5], o[6], o[7]);
            }
        }
#pragma unroll
        for (int c = 0; c < 8; c++) {
            atomicAdd(&st_s[0][cg * 8 + c], csum[c]);
            atomicAdd(&st_s[1][cg * 8 + c], csq[c]);
        }
        __syncthreads();
        atomicAdd(&ssum[t], st_s[0][t]);
        atomicAdd(&ssq[t],  st_s[1][t]);
    } else {
#pragma unroll
        for (int r = 0; r < 8; r++) {
            int row = row_base + rg * 8 + r;
            if (row < M) {
                float o[8];
#pragma unroll
                for (int cp = 0; cp < 4; cp++)
                    UNPACK2(o[2 * cp], o[2 * cp + 1], accp[r][cp]);
#pragma unroll
                for (int c = 0; c < 8; c++) o[c] = fmaxf(o[c] + bv[c], 0.f);
                float4* op = (float4*)(out + (size_t)row * D + cg * 8);
                op[0] = make_float4(o[0], o[1], o[2], o[3]);
                op[1] = make_float4(o[4], o[5], o[6], o[7]);
            }
        }
    }
}

// ---- fold BN stats + gamma/beta into per-feature scale/shift ----
__global__ void finalize_kernel(const float* __restrict__ ssum, const float* __restrict__ ssq,
                                const float* __restrict__ gamma, const float* __restrict__ beta,
                                float* __restrict__ scale, float* __restrict__ shift, float invN)
{
    int i = threadIdx.x;
    float m  = ssum[i] * invN;
    float v  = fmaf(ssq[i], invN, -m * m);
    float r  = rsqrtf(v + 1e-5f);
    float sc = r * __ldg(gamma + i);
    scale[i] = sc;
    shift[i] = fmaf(-m, sc, __ldg(beta + i));
}

extern "C" void kernel_launch(void* const* d_in, const int* in_sizes, int n_in,
                              void* d_out, int out_size) {
    const float* x     = (const float*)d_in[0];
    const int*   ei    = (const int*)d_in[1];       // int32 (JAX demotes int64)
    const float* ea    = (const float*)d_in[2];
    const float* W1    = (const float*)d_in[3];
    const float* b1    = (const float*)d_in[4];
    const float* gamma = (const float*)d_in[5];
    const float* beta  = (const float*)d_in[6];
    const float* W2    = (const float*)d_in[7];
    const float* b2    = (const float*)d_in[8];

    int M = in_sizes[0] / D;      // nodes
    int E = in_sizes[2] / D;      // edges
    int L = in_sizes[3] / (D * D);

    float *p_agg, *p_h, *p_x1, *p_sum, *p_sq, *p_scale, *p_shift;
    int *p_cnt, *p_rowptr, *p_fill, *p_perm, *p_se, *p_bsum;
    cudaGetSymbolAddress((void**)&p_agg,   g_agg);
    cudaGetSymbolAddress((void**)&p_h,     g_h);
    cudaGetSymbolAddress((void**)&p_x1,    g_x1);
    cudaGetSymbolAddress((void**)&p_sum,   g_sum);
    cudaGetSymbolAddress((void**)&p_sq,    g_sq);
    cudaGetSymbolAddress((void**)&p_scale, g_scale);
    cudaGetSymbolAddress((void**)&p_shift, g_shift);
    cudaGetSymbolAddress((void**)&p_cnt,    g_cnt);
    cudaGetSymbolAddress((void**)&p_rowptr, g_rowptr);
    cudaGetSymbolAddress((void**)&p_fill,   g_fill);
    cudaGetSymbolAddress((void**)&p_perm,   g_perm);
    cudaGetSymbolAddress((void**)&p_se,     g_se);
    cudaGetSymbolAddress((void**)&p_bsum,   g_bsum);

    int gemm_blocks = (M + TILE_M - 1) / TILE_M;
    int eb = (E + 255) / 256;
    int nbscan = (M + SCAN_B - 1) / SCAN_B;
    int agg_blocks = (M + 7) / 8;

    // ---- build CSR once (4 launches; scatter re-zeroes cnt for next replay)
    hist_kernel<<<eb, 256>>>(ei, p_cnt, E);
    scan1_kernel<<<nbscan, SCAN_B>>>(p_cnt, p_rowptr, p_bsum, M);
    scan23_kernel<<<nbscan, SCAN_B>>>(p_rowptr, p_fill, p_bsum, M);
    scatter_kernel<<<eb, 256>>>(ei, p_fill, p_perm, p_se, p_cnt, E, M);
    // after scatter: p_fill[v] == row end of v

    for (int l = 0; l < L; l++) {
        const float* xin = (l == 0) ? x : p_x1;
        float* xout = (l == L - 1) ? (float*)d_out : p_x1;

        agg_kernel<<<agg_blocks, 256>>>(xin, ea, p_rowptr, p_fill, p_perm, p_se,
                                        p_agg, p_sum, p_sq, M);
        gemm_kernel<0><<<gemm_blocks, 128>>>(p_agg,
                                             W1 + (size_t)l * D * D, b1 + (size_t)l * D,
                                             nullptr, nullptr, p_h, p_sum, p_sq, M);
        finalize_kernel<<<1, D>>>(p_sum, p_sq, gamma + (size_t)l * D, beta + (size_t)l * D,
                                  p_scale, p_shift, 1.0f / (float)M);
        gemm_kernel<1><<<gemm_blocks, 128>>>(p_h,
                                             W2 + (size_t)l * D * D, b2 + (size_t)l * D,
                                             p_scale, p_shift, xout, nullptr, nullptr, M);
    }
}